// round 15
// baseline (speedup 1.0000x reference)
#include <cuda_runtime.h>
#include <cstdint>

#define B_DIM 8192
#define N_DIM 4096
#define P_DIM 8
#define D_DIM 512

// ---------------- scratch (device globals; referenced ONLY in device code) ----------------
__device__ float g_h[(size_t)B_DIM * N_DIM];                 // tf32-rounded GEMM1 accumulators
__device__ float g_w1r[(size_t)P_DIM * D_DIM * D_DIM];       // tf32-rounded W1
__device__ float g_w2s[(size_t)P_DIM * D_DIM * D_DIM];       // tf32-rounded diag(s)·W2
__device__ float g_psum[64 * N_DIM];                         // per-mtile column sums
__device__ float g_psq[64 * N_DIM];                          // per-mtile column sumsq
__device__ float g_s[N_DIM];                                 // rstd * bn_weight
__device__ float g_t[N_DIM];                                 // bn_bias - mean_acc * s
__device__ float g_bias2f[N_DIM];                            // bias2 + t @ W2

// ---------------- tiling ----------------
constexpr int BM = 128;
constexpr int BN = 128;
constexpr int BK = 32;
constexpr int NKT = D_DIM / BK;        // 16
constexpr int STAGES = 3;
constexpr int LDA = 36;                // floats; A row stride (conflict-free feeds)
constexpr int LDB = 136;               // floats; B row stride
constexpr int A_FLOATS = BM * LDA;     // 4608
constexpr int B_FLOATS = BK * LDB;     // 4352
constexpr int STAGE_FLOATS = A_FLOATS + B_FLOATS;            // 8960
constexpr int SMEM_BYTES = STAGES * STAGE_FLOATS * 4;        // 107520 B

__device__ __forceinline__ float fast_sigmoid(float z) {
    return 1.0f / (1.0f + __expf(-z));
}
__device__ __forceinline__ uint32_t smem_u32(const void* p) {
    return (uint32_t)__cvta_generic_to_shared(p);
}
__device__ __forceinline__ void cp_async16(uint32_t dst, const void* src) {
    asm volatile("cp.async.cg.shared.global [%0], [%1], 16;" :: "r"(dst), "l"(src));
}
__device__ __forceinline__ uint32_t to_tf32(float f) {
    uint32_t u;
    asm("cvt.rna.tf32.f32 %0, %1;" : "=r"(u) : "f"(f));
    return u;
}
__device__ __forceinline__ void mma_tf32(float& c0, float& c1, float& c2, float& c3,
                                         uint32_t a0, uint32_t a1, uint32_t a2, uint32_t a3,
                                         uint32_t b0, uint32_t b1) {
    asm volatile(
        "mma.sync.aligned.m16n8k8.row.col.f32.tf32.tf32.f32 "
        "{%0,%1,%2,%3},{%4,%5,%6,%7},{%8,%9},{%0,%1,%2,%3};"
        : "+f"(c0), "+f"(c1), "+f"(c2), "+f"(c3)
        : "r"(a0), "r"(a1), "r"(a2), "r"(a3), "r"(b0), "r"(b1));
}

// MODE 0: g_h = tf32(x @ bdiag(g_w1r)) + fused partial column stats
//         (b1 cancels through BatchNorm; A=x needs in-loop cvt, B pre-rounded)
// MODE 1: out = gate(g_h @ g_w2s + g_bias2f + x)   (A, B both pre-rounded: no cvt)
template <int MODE>
__global__ void __launch_bounds__(256, 2)
gemm_mma(const float* __restrict__ A_ext,
         const float* __restrict__ x_res,
         const float* __restrict__ gamma,
         const float* __restrict__ beta,
         float* __restrict__ out)
{
    extern __shared__ __align__(16) float smem[];

    const int tid  = threadIdx.x;
    const int wid  = tid >> 5;
    const int lane = tid & 31;
    const int wm   = wid >> 2;       // 0..1  (64-row slabs)
    const int wn   = wid & 3;        // 0..3  (32-col slabs)
    const int lg   = lane >> 2;      // group 0..7
    const int lt   = lane & 3;       // 0..3

    const int ntile = blockIdx.x;    // 0..31
    const int mtile = blockIdx.y;    // 0..63
    const int p     = ntile >> 2;
    const int ecol0 = (ntile & 3) * BN;
    const int row0  = mtile * BM;

    // device-side selection of device globals (host must never pass them)
    const float* Abase = (MODE == 0 ? A_ext : (const float*)g_h)
                       + (size_t)row0 * N_DIM + p * D_DIM;
    const float* Wsel  = (MODE == 0) ? (const float*)g_w1r : (const float*)g_w2s;
    const float* Bbase = Wsel + (size_t)p * D_DIM * D_DIM + ecol0;

    const uint32_t smem_base = smem_u32(smem);

    auto load_stage = [&](int kt, int buf) {
        const uint32_t a_s = smem_base + (uint32_t)(buf * STAGE_FLOATS) * 4u;
        const uint32_t b_s = a_s + (uint32_t)A_FLOATS * 4u;
        const float* Ag = Abase + kt * BK;
        const float* Bg = Bbase + (size_t)(kt * BK) * D_DIM;
        #pragma unroll
        for (int q = 0; q < 4; q++) {                 // A: 128 rows x 8 f4
            const int idx = q * 256 + tid;            // 0..1023
            const int r = idx >> 3, c = idx & 7;
            cp_async16(a_s + (uint32_t)(r * LDA + c * 4) * 4u,
                       Ag + (size_t)r * N_DIM + c * 4);
        }
        #pragma unroll
        for (int q = 0; q < 4; q++) {                 // B: 32 rows x 32 f4
            const int idx = q * 256 + tid;
            const int r = idx >> 5, c = idx & 31;
            cp_async16(b_s + (uint32_t)(r * LDB + c * 4) * 4u,
                       Bg + (size_t)r * D_DIM + c * 4);
        }
        asm volatile("cp.async.commit_group;" ::: "memory");
    };

    float acc[4][4][4];
    #pragma unroll
    for (int i = 0; i < 4; i++)
        #pragma unroll
        for (int j = 0; j < 4; j++)
            #pragma unroll
            for (int k = 0; k < 4; k++) acc[i][j][k] = 0.0f;

    load_stage(0, 0);
    load_stage(1, 1);

    for (int kt = 0; kt < NKT; kt++) {
        if (kt == NKT - 1) asm volatile("cp.async.wait_group 0;" ::: "memory");
        else               asm volatile("cp.async.wait_group 1;" ::: "memory");
        __syncthreads();
        if (kt + 2 < NKT) load_stage(kt + 2, (kt + 2) % STAGES);

        const float* As = smem + (kt % STAGES) * STAGE_FLOATS;
        const float* Bs = As + A_FLOATS;

        #pragma unroll
        for (int k8 = 0; k8 < BK; k8 += 8) {
            uint32_t af[4][4];
            #pragma unroll
            for (int mi = 0; mi < 4; mi++) {
                const int rb = wm * 64 + mi * 16;
                if (MODE == 0) {   // A = x, needs rounding
                    af[mi][0] = to_tf32(As[(rb + lg) * LDA + k8 + lt]);
                    af[mi][1] = to_tf32(As[(rb + 8 + lg) * LDA + k8 + lt]);
                    af[mi][2] = to_tf32(As[(rb + lg) * LDA + k8 + 4 + lt]);
                    af[mi][3] = to_tf32(As[(rb + 8 + lg) * LDA + k8 + 4 + lt]);
                } else {           // A = g_h, pre-rounded bits
                    af[mi][0] = __float_as_uint(As[(rb + lg) * LDA + k8 + lt]);
                    af[mi][1] = __float_as_uint(As[(rb + 8 + lg) * LDA + k8 + lt]);
                    af[mi][2] = __float_as_uint(As[(rb + lg) * LDA + k8 + 4 + lt]);
                    af[mi][3] = __float_as_uint(As[(rb + 8 + lg) * LDA + k8 + 4 + lt]);
                }
            }
            uint32_t bf[4][2];     // B always pre-rounded
            #pragma unroll
            for (int ni = 0; ni < 4; ni++) {
                const int cb = wn * 32 + ni * 8;
                bf[ni][0] = __float_as_uint(Bs[(k8 + lt) * LDB + cb + lg]);
                bf[ni][1] = __float_as_uint(Bs[(k8 + 4 + lt) * LDB + cb + lg]);
            }
            #pragma unroll
            for (int mi = 0; mi < 4; mi++)
                #pragma unroll
                for (int ni = 0; ni < 4; ni++)
                    mma_tf32(acc[mi][ni][0], acc[mi][ni][1], acc[mi][ni][2], acc[mi][ni][3],
                             af[mi][0], af[mi][1], af[mi][2], af[mi][3],
                             bf[ni][0], bf[ni][1]);
        }
    }

    if (MODE == 0) {
        // ---- epilogue: store tf32-rounded h + fused deterministic column stats ----
        float s0[4], q0[4], s1[4], q1[4];
        #pragma unroll
        for (int ni = 0; ni < 4; ni++) { s0[ni] = q0[ni] = s1[ni] = q1[ni] = 0.0f; }

        #pragma unroll
        for (int mi = 0; mi < 4; mi++) {
            #pragma unroll
            for (int ni = 0; ni < 4; ni++) {
                const int gc = ntile * BN + wn * 32 + ni * 8 + 2 * lt;
                #pragma unroll
                for (int rr = 0; rr < 2; rr++) {
                    const int gr = row0 + wm * 64 + mi * 16 + lg + rr * 8;
                    const float v0 = __uint_as_float(to_tf32(acc[mi][ni][rr * 2 + 0]));
                    const float v1 = __uint_as_float(to_tf32(acc[mi][ni][rr * 2 + 1]));
                    *(float2*)((float*)g_h + (size_t)gr * N_DIM + gc) = make_float2(v0, v1);
                    s0[ni] += v0; q0[ni] += v0 * v0;
                    s1[ni] += v1; q1[ni] += v1 * v1;
                }
            }
        }
        // reduce over lg (lanes stride 4): lanes 0..3 (lg==0) end with warp totals
        #pragma unroll
        for (int ni = 0; ni < 4; ni++) {
            #pragma unroll
            for (int off = 16; off >= 4; off >>= 1) {
                s0[ni] += __shfl_down_sync(0xffffffffu, s0[ni], off);
                q0[ni] += __shfl_down_sync(0xffffffffu, q0[ni], off);
                s1[ni] += __shfl_down_sync(0xffffffffu, s1[ni], off);
                q1[ni] += __shfl_down_sync(0xffffffffu, q1[ni], off);
            }
        }
        __syncthreads();                    // stage buffers no longer needed
        float* ps = smem;                   // [2][128] sums
        float* pq = smem + 256;             // [2][128] sumsqs
        if (lane < 4) {
            #pragma unroll
            for (int ni = 0; ni < 4; ni++) {
                const int cl = wn * 32 + ni * 8 + 2 * lane;
                ps[wm * 128 + cl]     = s0[ni];
                ps[wm * 128 + cl + 1] = s1[ni];
                pq[wm * 128 + cl]     = q0[ni];
                pq[wm * 128 + cl + 1] = q1[ni];
            }
        }
        __syncthreads();
        if (tid < 128) {
            const size_t o = (size_t)mtile * N_DIM + ntile * BN + tid;
            g_psum[o] = ps[tid] + ps[128 + tid];
            g_psq[o]  = pq[tid] + pq[128 + tid];
        }
        return;
    }

    // ---- MODE 1 epilogue: bias + residual + gate, direct register -> global ----
    #pragma unroll
    for (int mi = 0; mi < 4; mi++) {
        #pragma unroll
        for (int ni = 0; ni < 4; ni++) {
            const int gc = ntile * BN + wn * 32 + ni * 8 + 2 * lt;
            const float2 b2v = *(const float2*)((const float*)g_bias2f + gc);
            const float2 gm = *(const float2*)(gamma + gc);
            const float2 bt = *(const float2*)(beta + gc);
            #pragma unroll
            for (int rr = 0; rr < 2; rr++) {
                const int gr = row0 + wm * 64 + mi * 16 + lg + rr * 8;
                const size_t gidx = (size_t)gr * N_DIM + gc;
                const float2 xv = *(const float2*)(x_res + gidx);
                float o30 = acc[mi][ni][rr * 2 + 0] + b2v.x + xv.x;
                float o31 = acc[mi][ni][rr * 2 + 1] + b2v.y + xv.y;
                float2 o;
                o.x = (gm.x + fast_sigmoid(bt.x * o30) * (1.0f - gm.x)) * o30;
                o.y = (gm.y + fast_sigmoid(bt.y * o31) * (1.0f - gm.y)) * o31;
                *(float2*)(out + gidx) = o;
            }
        }
    }
}

// ---------------- prep: round W1 to tf32 bits ----------------
__global__ void round_w1_kernel(const float* __restrict__ w1)
{
    const size_t i = (size_t)blockIdx.x * 256 + threadIdx.x;   // float4 index
    float4 v = *(const float4*)(w1 + i * 4);
    v.x = __uint_as_float(to_tf32(v.x));
    v.y = __uint_as_float(to_tf32(v.y));
    v.z = __uint_as_float(to_tf32(v.z));
    v.w = __uint_as_float(to_tf32(v.w));
    *(float4*)(g_w1r + i * 4) = v;
}

// ---------------- finalize stats: reduce 64 per-mtile partials ----------------
__global__ void finalize_stats_kernel(const float* __restrict__ bn_w,
                                      const float* __restrict__ bn_b)
{
    const int c = blockIdx.x * 256 + threadIdx.x;
    float s = 0.0f, q = 0.0f;
    #pragma unroll
    for (int k = 0; k < 64; k++) {
        s += g_psum[(size_t)k * N_DIM + c];
        q += g_psq[(size_t)k * N_DIM + c];
    }
    const float inv_b = 1.0f / (float)B_DIM;
    float mean = s * inv_b;                       // mean of rounded acc (b1 cancels)
    float var = q * inv_b - mean * mean;
    float rstd = rsqrtf(var + 1e-5f);
    float sc = rstd * bn_w[c];
    g_s[c] = sc;
    g_t[c] = bn_b[c] - mean * sc;
}

// g_w2s[row][*] = tf32(s[row] * w2[row][*])  (row = p*D+d; 128 float4 per row)
__global__ void scale_w2_kernel(const float* __restrict__ w2)
{
    const size_t i = (size_t)blockIdx.x * 256 + threadIdx.x;
    const int d_glob = (int)(i >> 7);
    float4 v = *(const float4*)(w2 + i * 4);
    const float sc = g_s[d_glob];
    v.x = __uint_as_float(to_tf32(v.x * sc));
    v.y = __uint_as_float(to_tf32(v.y * sc));
    v.z = __uint_as_float(to_tf32(v.z * sc));
    v.w = __uint_as_float(to_tf32(v.w * sc));
    *(float4*)(g_w2s + i * 4) = v;
}

// g_bias2f[e] = bias2[e] + sum_d t[p*D+d] * W2[p][d][e]   (full fp32)
__global__ void biasfold_kernel(const float* __restrict__ bias2, const float* __restrict__ w2)
{
    const int e = blockIdx.x * 128 + threadIdx.x;
    const int p = e / D_DIM;
    const int el = e % D_DIM;
    const float* wp = w2 + (size_t)p * D_DIM * D_DIM + el;
    const float* tp = g_t + p * D_DIM;
    float c = 0.0f;
    #pragma unroll 8
    for (int d = 0; d < D_DIM; d++)
        c += tp[d] * wp[(size_t)d * D_DIM];
    g_bias2f[e] = bias2[e] + c;
}

// ---------------- launch ----------------
extern "C" void kernel_launch(void* const* d_in, const int* in_sizes, int n_in,
                              void* d_out, int out_size)
{
    (void)in_sizes; (void)n_in; (void)out_size;
    const float* x   = (const float*)d_in[0];
    const float* w1  = (const float*)d_in[1];
    const float* w2  = (const float*)d_in[3];
    const float* b2  = (const float*)d_in[4];
    const float* bnw = (const float*)d_in[5];
    const float* bnb = (const float*)d_in[6];
    const float* g3  = (const float*)d_in[7];
    const float* be3 = (const float*)d_in[8];
    float* out = (float*)d_out;

    cudaFuncSetAttribute(gemm_mma<0>, cudaFuncAttributeMaxDynamicSharedMemorySize, SMEM_BYTES);
    cudaFuncSetAttribute(gemm_mma<1>, cudaFuncAttributeMaxDynamicSharedMemorySize, SMEM_BYTES);

    dim3 ggrid(N_DIM / BN, B_DIM / BM);   // (32, 64)
    const int wquads = P_DIM * D_DIM * D_DIM / 4;   // 524288 float4s

    // 0) pre-round W1 to tf32
    round_w1_kernel<<<wquads / 256, 256>>>(w1);
    // 1) g_h = tf32(x @ bdiag(W1)) + fused partial column stats
    gemm_mma<0><<<ggrid, 256, SMEM_BYTES>>>(x, nullptr, nullptr, nullptr, nullptr);
    // 2) fold BN into (s, t)
    finalize_stats_kernel<<<N_DIM / 256, 256>>>(bnw, bnb);
    // 3) g_w2s = tf32(diag(s)·W2) ; g_bias2f = b2 + t@W2
    scale_w2_kernel<<<wquads / 256, 256>>>(w2);
    biasfold_kernel<<<N_DIM / 128, 128>>>(b2, w2);
    // 4) out = gate(g_h @ g_w2s + g_bias2f + x)
    gemm_mma<1><<<ggrid, 256, SMEM_BYTES>>>(x, x, g3, be3, out);
}

// round 16
// speedup vs baseline: 1.0025x; 1.0025x over previous
#include <cuda_runtime.h>
#include <cstdint>

#define B_DIM 8192
#define N_DIM 4096
#define P_DIM 8
#define D_DIM 512

// ---------------- scratch (device globals; referenced ONLY in device code) ----------------
__device__ float g_h[(size_t)B_DIM * N_DIM];                 // tf32-rounded GEMM1 accumulators
__device__ float g_w1r[(size_t)P_DIM * D_DIM * D_DIM];       // tf32-rounded W1
__device__ float g_w2s[(size_t)P_DIM * D_DIM * D_DIM];       // tf32-rounded diag(s)·W2
__device__ float g_psum[64 * N_DIM];                         // per-mtile column sums
__device__ float g_psq[64 * N_DIM];                          // per-mtile column sumsq
__device__ float g_s[N_DIM];                                 // rstd * bn_weight
__device__ float g_t[N_DIM];                                 // bn_bias - mean_acc * s
__device__ float g_bias2f[N_DIM];                            // bias2 + t @ W2

// ---------------- tiling ----------------
constexpr int BM = 128;
constexpr int BN = 128;
constexpr int BK = 32;
constexpr int NKT = D_DIM / BK;        // 16
constexpr int STAGES = 3;
constexpr int LDA = 36;                // floats; A row stride (conflict-free feeds)
constexpr int LDB = 136;               // floats; B row stride
constexpr int A_FLOATS = BM * LDA;     // 4608
constexpr int B_FLOATS = BK * LDB;     // 4352
constexpr int STAGE_FLOATS = A_FLOATS + B_FLOATS;            // 8960
constexpr int SMEM_BYTES = STAGES * STAGE_FLOATS * 4;        // 107520 B

__device__ __forceinline__ float fast_sigmoid(float z) {
    return 1.0f / (1.0f + __expf(-z));
}
__device__ __forceinline__ uint32_t smem_u32(const void* p) {
    return (uint32_t)__cvta_generic_to_shared(p);
}
__device__ __forceinline__ void cp_async16(uint32_t dst, const void* src) {
    asm volatile("cp.async.cg.shared.global [%0], [%1], 16;" :: "r"(dst), "l"(src));
}
__device__ __forceinline__ uint32_t to_tf32(float f) {
    uint32_t u;
    asm("cvt.rna.tf32.f32 %0, %1;" : "=r"(u) : "f"(f));
    return u;
}
__device__ __forceinline__ void mma_tf32(float& c0, float& c1, float& c2, float& c3,
                                         uint32_t a0, uint32_t a1, uint32_t a2, uint32_t a3,
                                         uint32_t b0, uint32_t b1) {
    asm volatile(
        "mma.sync.aligned.m16n8k8.row.col.f32.tf32.tf32.f32 "
        "{%0,%1,%2,%3},{%4,%5,%6,%7},{%8,%9},{%0,%1,%2,%3};"
        : "+f"(c0), "+f"(c1), "+f"(c2), "+f"(c3)
        : "r"(a0), "r"(a1), "r"(a2), "r"(a3), "r"(b0), "r"(b1));
}

// MODE 0: g_h = tf32(x @ bdiag(g_w1r)) + fused partial column stats
//         (b1 cancels through BatchNorm; A=x needs in-loop cvt, B pre-rounded)
// MODE 1: out = gate(g_h @ g_w2s + g_bias2f + x)   (A, B both pre-rounded: no cvt)
template <int MODE>
__global__ void __launch_bounds__(256, 2)
gemm_mma(const float* __restrict__ A_ext,
         const float* __restrict__ x_res,
         const float* __restrict__ gamma,
         const float* __restrict__ beta,
         float* __restrict__ out)
{
    extern __shared__ __align__(16) float smem[];

    const int tid  = threadIdx.x;
    const int wid  = tid >> 5;
    const int lane = tid & 31;
    const int wm   = wid >> 2;       // 0..1  (64-row slabs)
    const int wn   = wid & 3;        // 0..3  (32-col slabs)
    const int lg   = lane >> 2;      // group 0..7
    const int lt   = lane & 3;       // 0..3

    const int ntile = blockIdx.x;    // 0..31
    const int mtile = blockIdx.y;    // 0..63
    const int p     = ntile >> 2;
    const int ecol0 = (ntile & 3) * BN;
    const int row0  = mtile * BM;

    // device-side selection of device globals (host must never pass them)
    const float* Abase = (MODE == 0 ? A_ext : (const float*)g_h)
                       + (size_t)row0 * N_DIM + p * D_DIM;
    const float* Wsel  = (MODE == 0) ? (const float*)g_w1r : (const float*)g_w2s;
    const float* Bbase = Wsel + (size_t)p * D_DIM * D_DIM + ecol0;

    const uint32_t smem_base = smem_u32(smem);

    auto load_stage = [&](int kt, int buf) {
        const uint32_t a_s = smem_base + (uint32_t)(buf * STAGE_FLOATS) * 4u;
        const uint32_t b_s = a_s + (uint32_t)A_FLOATS * 4u;
        const float* Ag = Abase + kt * BK;
        const float* Bg = Bbase + (size_t)(kt * BK) * D_DIM;
        #pragma unroll
        for (int q = 0; q < 4; q++) {                 // A: 128 rows x 8 f4
            const int idx = q * 256 + tid;            // 0..1023
            const int r = idx >> 3, c = idx & 7;
            cp_async16(a_s + (uint32_t)(r * LDA + c * 4) * 4u,
                       Ag + (size_t)r * N_DIM + c * 4);
        }
        #pragma unroll
        for (int q = 0; q < 4; q++) {                 // B: 32 rows x 32 f4
            const int idx = q * 256 + tid;
            const int r = idx >> 5, c = idx & 31;
            cp_async16(b_s + (uint32_t)(r * LDB + c * 4) * 4u,
                       Bg + (size_t)r * D_DIM + c * 4);
        }
        asm volatile("cp.async.commit_group;" ::: "memory");
    };

    float acc[4][4][4];
    #pragma unroll
    for (int i = 0; i < 4; i++)
        #pragma unroll
        for (int j = 0; j < 4; j++)
            #pragma unroll
            for (int k = 0; k < 4; k++) acc[i][j][k] = 0.0f;

    load_stage(0, 0);
    load_stage(1, 1);

    for (int kt = 0; kt < NKT; kt++) {
        if (kt == NKT - 1) asm volatile("cp.async.wait_group 0;" ::: "memory");
        else               asm volatile("cp.async.wait_group 1;" ::: "memory");
        __syncthreads();
        if (kt + 2 < NKT) load_stage(kt + 2, (kt + 2) % STAGES);

        const float* As = smem + (kt % STAGES) * STAGE_FLOATS;
        const float* Bs = As + A_FLOATS;

        #pragma unroll
        for (int k8 = 0; k8 < BK; k8 += 8) {
            uint32_t af[4][4];
            #pragma unroll
            for (int mi = 0; mi < 4; mi++) {
                const int rb = wm * 64 + mi * 16;
                if (MODE == 0) {   // A = x, needs rounding
                    af[mi][0] = to_tf32(As[(rb + lg) * LDA + k8 + lt]);
                    af[mi][1] = to_tf32(As[(rb + 8 + lg) * LDA + k8 + lt]);
                    af[mi][2] = to_tf32(As[(rb + lg) * LDA + k8 + 4 + lt]);
                    af[mi][3] = to_tf32(As[(rb + 8 + lg) * LDA + k8 + 4 + lt]);
                } else {           // A = g_h, pre-rounded bits
                    af[mi][0] = __float_as_uint(As[(rb + lg) * LDA + k8 + lt]);
                    af[mi][1] = __float_as_uint(As[(rb + 8 + lg) * LDA + k8 + lt]);
                    af[mi][2] = __float_as_uint(As[(rb + lg) * LDA + k8 + 4 + lt]);
                    af[mi][3] = __float_as_uint(As[(rb + 8 + lg) * LDA + k8 + 4 + lt]);
                }
            }
            uint32_t bf[4][2];     // B always pre-rounded
            #pragma unroll
            for (int ni = 0; ni < 4; ni++) {
                const int cb = wn * 32 + ni * 8;
                bf[ni][0] = __float_as_uint(Bs[(k8 + lt) * LDB + cb + lg]);
                bf[ni][1] = __float_as_uint(Bs[(k8 + 4 + lt) * LDB + cb + lg]);
            }
            #pragma unroll
            for (int mi = 0; mi < 4; mi++)
                #pragma unroll
                for (int ni = 0; ni < 4; ni++)
                    mma_tf32(acc[mi][ni][0], acc[mi][ni][1], acc[mi][ni][2], acc[mi][ni][3],
                             af[mi][0], af[mi][1], af[mi][2], af[mi][3],
                             bf[ni][0], bf[ni][1]);
        }
    }

    if (MODE == 0) {
        // ---- epilogue: store tf32-rounded h + fused deterministic column stats ----
        float s0[4], q0[4], s1[4], q1[4];
        #pragma unroll
        for (int ni = 0; ni < 4; ni++) { s0[ni] = q0[ni] = s1[ni] = q1[ni] = 0.0f; }

        #pragma unroll
        for (int mi = 0; mi < 4; mi++) {
            #pragma unroll
            for (int ni = 0; ni < 4; ni++) {
                const int gc = ntile * BN + wn * 32 + ni * 8 + 2 * lt;
                #pragma unroll
                for (int rr = 0; rr < 2; rr++) {
                    const int gr = row0 + wm * 64 + mi * 16 + lg + rr * 8;
                    const float v0 = __uint_as_float(to_tf32(acc[mi][ni][rr * 2 + 0]));
                    const float v1 = __uint_as_float(to_tf32(acc[mi][ni][rr * 2 + 1]));
                    *(float2*)((float*)g_h + (size_t)gr * N_DIM + gc) = make_float2(v0, v1);
                    s0[ni] += v0; q0[ni] += v0 * v0;
                    s1[ni] += v1; q1[ni] += v1 * v1;
                }
            }
        }
        // reduce over lg (lanes stride 4): lanes 0..3 (lg==0) end with warp totals
        #pragma unroll
        for (int ni = 0; ni < 4; ni++) {
            #pragma unroll
            for (int off = 16; off >= 4; off >>= 1) {
                s0[ni] += __shfl_down_sync(0xffffffffu, s0[ni], off);
                q0[ni] += __shfl_down_sync(0xffffffffu, q0[ni], off);
                s1[ni] += __shfl_down_sync(0xffffffffu, s1[ni], off);
                q1[ni] += __shfl_down_sync(0xffffffffu, q1[ni], off);
            }
        }
        __syncthreads();                    // stage buffers no longer needed
        float* ps = smem;                   // [2][128] sums
        float* pq = smem + 256;             // [2][128] sumsqs
        if (lane < 4) {
            #pragma unroll
            for (int ni = 0; ni < 4; ni++) {
                const int cl = wn * 32 + ni * 8 + 2 * lane;
                ps[wm * 128 + cl]     = s0[ni];
                ps[wm * 128 + cl + 1] = s1[ni];
                pq[wm * 128 + cl]     = q0[ni];
                pq[wm * 128 + cl + 1] = q1[ni];
            }
        }
        __syncthreads();
        if (tid < 128) {
            const size_t o = (size_t)mtile * N_DIM + ntile * BN + tid;
            g_psum[o] = ps[tid] + ps[128 + tid];
            g_psq[o]  = pq[tid] + pq[128 + tid];
        }
        return;
    }

    // ---- MODE 1 epilogue: bias + residual + gate, direct register -> global ----
    #pragma unroll
    for (int mi = 0; mi < 4; mi++) {
        #pragma unroll
        for (int ni = 0; ni < 4; ni++) {
            const int gc = ntile * BN + wn * 32 + ni * 8 + 2 * lt;
            const float2 b2v = *(const float2*)((const float*)g_bias2f + gc);
            const float2 gm = *(const float2*)(gamma + gc);
            const float2 bt = *(const float2*)(beta + gc);
            #pragma unroll
            for (int rr = 0; rr < 2; rr++) {
                const int gr = row0 + wm * 64 + mi * 16 + lg + rr * 8;
                const size_t gidx = (size_t)gr * N_DIM + gc;
                const float2 xv = *(const float2*)(x_res + gidx);
                float o30 = acc[mi][ni][rr * 2 + 0] + b2v.x + xv.x;
                float o31 = acc[mi][ni][rr * 2 + 1] + b2v.y + xv.y;
                float2 o;
                o.x = (gm.x + fast_sigmoid(bt.x * o30) * (1.0f - gm.x)) * o30;
                o.y = (gm.y + fast_sigmoid(bt.y * o31) * (1.0f - gm.y)) * o31;
                *(float2*)(out + gidx) = o;
            }
        }
    }
}

// ---------------- prep: round W1 to tf32 bits ----------------
__global__ void round_w1_kernel(const float* __restrict__ w1)
{
    const size_t i = (size_t)blockIdx.x * 256 + threadIdx.x;   // float4 index
    float4 v = *(const float4*)(w1 + i * 4);
    v.x = __uint_as_float(to_tf32(v.x));
    v.y = __uint_as_float(to_tf32(v.y));
    v.z = __uint_as_float(to_tf32(v.z));
    v.w = __uint_as_float(to_tf32(v.w));
    *(float4*)(g_w1r + i * 4) = v;
}

// ---------------- finalize stats: reduce 64 per-mtile partials ----------------
__global__ void finalize_stats_kernel(const float* __restrict__ bn_w,
                                      const float* __restrict__ bn_b)
{
    const int c = blockIdx.x * 256 + threadIdx.x;
    float s = 0.0f, q = 0.0f;
    #pragma unroll
    for (int k = 0; k < 64; k++) {
        s += g_psum[(size_t)k * N_DIM + c];
        q += g_psq[(size_t)k * N_DIM + c];
    }
    const float inv_b = 1.0f / (float)B_DIM;
    float mean = s * inv_b;                       // mean of rounded acc (b1 cancels)
    float var = q * inv_b - mean * mean;
    float rstd = rsqrtf(var + 1e-5f);
    float sc = rstd * bn_w[c];
    g_s[c] = sc;
    g_t[c] = bn_b[c] - mean * sc;
}

// g_w2s[row][*] = tf32(s[row] * w2[row][*])  (row = p*D+d; 128 float4 per row)
__global__ void scale_w2_kernel(const float* __restrict__ w2)
{
    const size_t i = (size_t)blockIdx.x * 256 + threadIdx.x;
    const int d_glob = (int)(i >> 7);
    float4 v = *(const float4*)(w2 + i * 4);
    const float sc = g_s[d_glob];
    v.x = __uint_as_float(to_tf32(v.x * sc));
    v.y = __uint_as_float(to_tf32(v.y * sc));
    v.z = __uint_as_float(to_tf32(v.z * sc));
    v.w = __uint_as_float(to_tf32(v.w * sc));
    *(float4*)(g_w2s + i * 4) = v;
}

// g_bias2f[e] = bias2[e] + sum_d t[p*D+d] * W2[p][d][e]   (full fp32)
__global__ void biasfold_kernel(const float* __restrict__ bias2, const float* __restrict__ w2)
{
    const int e = blockIdx.x * 128 + threadIdx.x;
    const int p = e / D_DIM;
    const int el = e % D_DIM;
    const float* wp = w2 + (size_t)p * D_DIM * D_DIM + el;
    const float* tp = g_t + p * D_DIM;
    float c = 0.0f;
    #pragma unroll 8
    for (int d = 0; d < D_DIM; d++)
        c += tp[d] * wp[(size_t)d * D_DIM];
    g_bias2f[e] = bias2[e] + c;
}

// ---------------- launch ----------------
extern "C" void kernel_launch(void* const* d_in, const int* in_sizes, int n_in,
                              void* d_out, int out_size)
{
    (void)in_sizes; (void)n_in; (void)out_size;
    const float* x   = (const float*)d_in[0];
    const float* w1  = (const float*)d_in[1];
    const float* w2  = (const float*)d_in[3];
    const float* b2  = (const float*)d_in[4];
    const float* bnw = (const float*)d_in[5];
    const float* bnb = (const float*)d_in[6];
    const float* g3  = (const float*)d_in[7];
    const float* be3 = (const float*)d_in[8];
    float* out = (float*)d_out;

    cudaFuncSetAttribute(gemm_mma<0>, cudaFuncAttributeMaxDynamicSharedMemorySize, SMEM_BYTES);
    cudaFuncSetAttribute(gemm_mma<1>, cudaFuncAttributeMaxDynamicSharedMemorySize, SMEM_BYTES);

    dim3 ggrid(N_DIM / BN, B_DIM / BM);   // (32, 64)
    const int wquads = P_DIM * D_DIM * D_DIM / 4;   // 524288 float4s

    // 0) pre-round W1 to tf32
    round_w1_kernel<<<wquads / 256, 256>>>(w1);
    // 1) g_h = tf32(x @ bdiag(W1)) + fused partial column stats
    gemm_mma<0><<<ggrid, 256, SMEM_BYTES>>>(x, nullptr, nullptr, nullptr, nullptr);
    // 2) fold BN into (s, t)
    finalize_stats_kernel<<<N_DIM / 256, 256>>>(bnw, bnb);
    // 3) g_w2s = tf32(diag(s)·W2) ; g_bias2f = b2 + t@W2
    scale_w2_kernel<<<wquads / 256, 256>>>(w2);
    biasfold_kernel<<<N_DIM / 128, 128>>>(b2, w2);
    // 4) out = gate(g_h @ g_w2s + g_bias2f + x)
    gemm_mma<1><<<ggrid, 256, SMEM_BYTES>>>(x, x, g3, be3, out);
}